// round 1
// baseline (speedup 1.0000x reference)
#include <cuda_runtime.h>
#include <math.h>
#include <float.h>

// Problem-fixed shapes (from reference setup_inputs)
#define N_TOT   200000
#define F_IN    602
#define N1      120000
#define N1D     30000
#define E1      960000
#define N2D     6000
#define E2      192000
#define C1      64
#define H1      8
#define OUTC    41

// ---------------- scratch (static device globals; no allocation) ------------
__device__ float g_hs1[(size_t)N1 * C1];     // layer-1 transformed features
__device__ float g_as1[N1 * H1];             // per-node src attention logits
__device__ float g_ad1[N1D * H1];            // per-dst-node dst attention logits
__device__ float g_out1[N1D * C1];           // layer-1 output (post bias+ELU)
__device__ float g_hs2[N1D * OUTC];          // layer-2 transformed features
__device__ float g_as2[N1D];
__device__ float g_ad2[N2D];
__device__ int   g_counts[N1D];
__device__ int   g_cursor[N1D];
__device__ int   g_offs1[N1D + 1];
__device__ int   g_offs2[N2D + 1];
__device__ int   g_ssrc1[E1];                // edge src sorted by dst
__device__ int   g_ssrc2[E2];

// ---------------- GEMM1: hs1 = x[n_id1] @ W1 ; fused as1 -------------------
// Block: 256 threads, tile 256 rows x 64 cols, K-chunks of 8.
// Thread (tx=tid&7, ty=tid>>3) computes 8 rows x 8 cols; tx's 8 cols == head tx,
// so per-row att_src dot completes within one thread (no cross-thread reduce).
__global__ __launch_bounds__(256, 2)
void k_gemm1(const float* __restrict__ x, const int* __restrict__ n_id,
             const float* __restrict__ W, const float* __restrict__ att_src) {
    __shared__ float As[8][256];
    __shared__ float Bs[8][64];
    __shared__ int   rid[256];
    int tid  = threadIdx.x;
    int row0 = blockIdx.x * 256;
    {
        int r = row0 + tid;
        rid[tid] = (r < N1) ? n_id[r] : -1;
    }
    __syncthreads();
    int myrow = rid[tid];
    const float* xrow = x + (myrow < 0 ? 0 : (size_t)myrow * F_IN);
    int tx = tid & 7, ty = tid >> 3;
    float acc[8][8];
#pragma unroll
    for (int i = 0; i < 8; i++)
#pragma unroll
        for (int j = 0; j < 8; j++) acc[i][j] = 0.f;

    for (int k0 = 0; k0 < F_IN; k0 += 8) {
        // A chunk: each thread loads 8 consecutive floats of its own row.
        // Row base + k0 is always 8B aligned (602*4 % 8 == 0) -> float2 loads.
        if (k0 + 8 <= F_IN && myrow >= 0) {
            const float2* p = (const float2*)(xrow + k0);
            float2 v0 = p[0], v1 = p[1], v2 = p[2], v3 = p[3];
            As[0][tid] = v0.x; As[1][tid] = v0.y;
            As[2][tid] = v1.x; As[3][tid] = v1.y;
            As[4][tid] = v2.x; As[5][tid] = v2.y;
            As[6][tid] = v3.x; As[7][tid] = v3.y;
        } else {
#pragma unroll
            for (int k = 0; k < 8; k++) {
                int kk = k0 + k;
                As[k][tid] = (myrow >= 0 && kk < F_IN) ? xrow[kk] : 0.f;
            }
        }
        // B chunk: 8x64
#pragma unroll
        for (int i = 0; i < 2; i++) {
            int idx = tid + i * 256;
            int k = idx >> 6, c = idx & 63;
            int kk = k0 + k;
            Bs[k][c] = (kk < F_IN) ? W[kk * 64 + c] : 0.f;
        }
        __syncthreads();
#pragma unroll
        for (int k = 0; k < 8; k++) {
            float4 a0 = *(const float4*)&As[k][ty * 8];
            float4 a1 = *(const float4*)&As[k][ty * 8 + 4];
            float4 b0 = *(const float4*)&Bs[k][tx * 8];
            float4 b1 = *(const float4*)&Bs[k][tx * 8 + 4];
            float a[8] = {a0.x, a0.y, a0.z, a0.w, a1.x, a1.y, a1.z, a1.w};
            float b[8] = {b0.x, b0.y, b0.z, b0.w, b1.x, b1.y, b1.z, b1.w};
#pragma unroll
            for (int i = 0; i < 8; i++)
#pragma unroll
                for (int j = 0; j < 8; j++) acc[i][j] = fmaf(a[i], b[j], acc[i][j]);
        }
        __syncthreads();
    }
    // Epilogue: store hs1 + fused per-head att_src dot
    float av[8];
#pragma unroll
    for (int j = 0; j < 8; j++) av[j] = att_src[tx * 8 + j];
#pragma unroll
    for (int i = 0; i < 8; i++) {
        int rr = row0 + ty * 8 + i;
        if (rr < N1) {
            float s = 0.f;
            float* o = &g_hs1[(size_t)rr * 64 + tx * 8];
#pragma unroll
            for (int j = 0; j < 8; j++) { o[j] = acc[i][j]; s = fmaf(acc[i][j], av[j], s); }
            g_as1[rr * 8 + tx] = s;
        }
    }
}

// ---------------- ad1: per-dst attention logits ----------------------------
__global__ void k_ad1(const int* __restrict__ res1, const float* __restrict__ att_dst) {
    int idx = blockIdx.x * blockDim.x + threadIdx.x;
    if (idx >= N1D * H1) return;
    int j = idx >> 3, h = idx & 7;
    int node = res1[j];
    const float* hp = &g_hs1[(size_t)node * 64 + h * 8];
    const float* ap = &att_dst[h * 8];
    float s = 0.f;
#pragma unroll
    for (int c = 0; c < 8; c++) s = fmaf(hp[c], ap[c], s);
    g_ad1[idx] = s;
}

// ---------------- CSR build ------------------------------------------------
__global__ void k_zero() {
    int i = blockIdx.x * blockDim.x + threadIdx.x;
    if (i < N1D) { g_counts[i] = 0; g_cursor[i] = 0; }
}

__global__ void k_hist(const int* __restrict__ dst, int E) {
    int i = blockIdx.x * blockDim.x + threadIdx.x;
    if (i < E) atomicAdd(&g_counts[dst[i]], 1);
}

__global__ void k_scan(int n, int layer) {
    __shared__ int sh[1024];
    int tid = threadIdx.x;
    int* offs = layer ? g_offs2 : g_offs1;
    int ipt = (n + 1023) / 1024;
    int beg = tid * ipt, end = min(n, beg + ipt);
    int s = 0;
    for (int i = beg; i < end; i++) s += g_counts[i];
    sh[tid] = s;
    __syncthreads();
    for (int d = 1; d < 1024; d <<= 1) {
        int v = (tid >= d) ? sh[tid - d] : 0;
        __syncthreads();
        if (tid >= d) sh[tid] += v;
        __syncthreads();
    }
    int run = sh[tid] - s;   // exclusive prefix
    for (int i = beg; i < end; i++) { offs[i] = run; run += g_counts[i]; }
    if (tid == 1023) offs[n] = run;
}

__global__ void k_scatter(const int* __restrict__ dst, const int* __restrict__ src,
                          int E, int layer) {
    int i = blockIdx.x * blockDim.x + threadIdx.x;
    if (i >= E) return;
    int d = dst[i];
    const int* offs = layer ? g_offs2 : g_offs1;
    int* out = layer ? g_ssrc2 : g_ssrc1;
    int pos = atomicAdd(&g_cursor[d], 1);
    out[offs[d] + pos] = src[i];
}

// ---------------- layer-1 aggregation: 1 warp / dst ------------------------
// Pass A: online softmax over edges, 4 edges x 8 heads per warp-iteration.
// Pass B: weighted accumulation, lane owns 2 of 64 channels.
__global__ void k_agg1(const float* __restrict__ bias) {
    int w = (blockIdx.x * blockDim.x + threadIdx.x) >> 5;
    int lane = threadIdx.x & 31;
    if (w >= N1D) return;
    int off0 = g_offs1[w], off1 = g_offs1[w + 1];
    int deg = off1 - off0;
    int h = lane & 7, eg = lane >> 3;
    float adh = g_ad1[w * 8 + h];
    float m = -FLT_MAX, s = 0.f;
    for (int i = eg; i < deg; i += 4) {
        int src = g_ssrc1[off0 + i];
        float e = g_as1[src * 8 + h] + adh;
        e = (e > 0.f) ? e : 0.2f * e;
        float mn = fmaxf(m, e);
        s = s * __expf(m - mn) + __expf(e - mn);
        m = mn;
    }
#pragma unroll
    for (int d2 = 8; d2 <= 16; d2 <<= 1) {
        float m2 = __shfl_xor_sync(0xffffffffu, m, d2);
        float s2 = __shfl_xor_sync(0xffffffffu, s, d2);
        float mn = fmaxf(m, m2);
        s = s * __expf(m - mn) + s2 * __expf(m2 - mn);
        m = mn;
    }
    int hc = lane >> 2;   // head for my 2 channels (cols 2*lane, 2*lane+1)
    float mh  = __shfl_sync(0xffffffffu, m, hc);
    float sh_ = __shfl_sync(0xffffffffu, s, hc);
    float inv = (sh_ > 0.f) ? 1.f / sh_ : 0.f;
    float adc = g_ad1[w * 8 + hc];
    float acc0 = 0.f, acc1 = 0.f;
    for (int i = 0; i < deg; i++) {
        int src = g_ssrc1[off0 + i];
        float e = g_as1[src * 8 + hc] + adc;
        e = (e > 0.f) ? e : 0.2f * e;
        float al = __expf(e - mh) * inv;
        float2 hv = *(const float2*)&g_hs1[(size_t)src * 64 + 2 * lane];
        acc0 = fmaf(al, hv.x, acc0);
        acc1 = fmaf(al, hv.y, acc1);
    }
    int c0 = 2 * lane;
    float v0 = acc0 + bias[c0], v1 = acc1 + bias[c0 + 1];
    v0 = (v0 > 0.f) ? v0 : expm1f(v0);   // ELU
    v1 = (v1 > 0.f) ? v1 : expm1f(v1);
    *(float2*)&g_out1[w * 64 + c0] = make_float2(v0, v1);
}

// ---------------- GEMM2: hs2 = out1 @ W2 -----------------------------------
__global__ void k_gemm2(const float* __restrict__ W2) {
    __shared__ float Asm[32][65];
    __shared__ float Wt[OUTC][65];
    int tid = threadIdx.x;
    int row0 = blockIdx.x * 32;
    for (int i = tid; i < 32 * 64; i += 256) {
        int r = i >> 6, k = i & 63;
        int row = row0 + r;
        Asm[r][k] = (row < N1D) ? g_out1[row * 64 + k] : 0.f;
    }
    for (int i = tid; i < OUTC * 64; i += 256) {
        int c = i >> 6, k = i & 63;
        Wt[c][k] = W2[k * OUTC + c];
    }
    __syncthreads();
    for (int o = tid; o < 32 * OUTC; o += 256) {
        int r = o / OUTC, c = o - r * OUTC;
        int row = row0 + r;
        if (row >= N1D) continue;
        float s = 0.f;
#pragma unroll
        for (int k = 0; k < 64; k++) s = fmaf(Asm[r][k], Wt[c][k], s);
        g_hs2[row * OUTC + c] = s;
    }
}

// ---------------- as2 / ad2 ------------------------------------------------
__global__ void k_asad2(const int* __restrict__ res2, const float* __restrict__ asw,
                        const float* __restrict__ adw) {
    int i = blockIdx.x * blockDim.x + threadIdx.x;
    if (i < N1D) {
        const float* hp = &g_hs2[i * OUTC];
        float s = 0.f;
#pragma unroll
        for (int c = 0; c < OUTC; c++) s = fmaf(hp[c], asw[c], s);
        g_as2[i] = s;
    } else if (i < N1D + N2D) {
        int j = i - N1D;
        const float* hp = &g_hs2[res2[j] * OUTC];
        float s = 0.f;
#pragma unroll
        for (int c = 0; c < OUTC; c++) s = fmaf(hp[c], adw[c], s);
        g_ad2[j] = s;
    }
}

// ---------------- layer-2 aggregation + log_softmax: 1 warp / dst ----------
__global__ void k_agg2(const float* __restrict__ bias, float* __restrict__ out) {
    int w = (blockIdx.x * blockDim.x + threadIdx.x) >> 5;
    int lane = threadIdx.x & 31;
    if (w >= N2D) return;
    int off0 = g_offs2[w], off1 = g_offs2[w + 1];
    int deg = off1 - off0;
    float add = g_ad2[w];
    float m = -FLT_MAX, s = 0.f;
    for (int i = lane; i < deg; i += 32) {
        int src = g_ssrc2[off0 + i];
        float e = g_as2[src] + add;
        e = (e > 0.f) ? e : 0.2f * e;
        float mn = fmaxf(m, e);
        s = s * __expf(m - mn) + __expf(e - mn);
        m = mn;
    }
#pragma unroll
    for (int d2 = 1; d2 < 32; d2 <<= 1) {
        float m2 = __shfl_xor_sync(0xffffffffu, m, d2);
        float s2 = __shfl_xor_sync(0xffffffffu, s, d2);
        float mn = fmaxf(m, m2);
        s = s * __expf(m - mn) + s2 * __expf(m2 - mn);
        m = mn;
    }
    float inv = (s > 0.f) ? 1.f / s : 0.f;
    float acc0 = 0.f, acc1 = 0.f;
    bool hi = (lane + 32) < OUTC;
    for (int i = 0; i < deg; i++) {
        int src = g_ssrc2[off0 + i];
        float e = g_as2[src] + add;
        e = (e > 0.f) ? e : 0.2f * e;
        float al = __expf(e - m) * inv;
        const float* hp = &g_hs2[src * OUTC];
        acc0 = fmaf(al, hp[lane], acc0);
        if (hi) acc1 = fmaf(al, hp[lane + 32], acc1);
    }
    float x0 = acc0 + bias[lane];
    float x1 = hi ? (acc1 + bias[lane + 32]) : -FLT_MAX;
    // log_softmax over 41 columns
    float mx = fmaxf(x0, x1);
#pragma unroll
    for (int d2 = 1; d2 < 32; d2 <<= 1) mx = fmaxf(mx, __shfl_xor_sync(0xffffffffu, mx, d2));
    float se = expf(x0 - mx) + (hi ? expf(x1 - mx) : 0.f);
#pragma unroll
    for (int d2 = 1; d2 < 32; d2 <<= 1) se += __shfl_xor_sync(0xffffffffu, se, d2);
    float lse = logf(se);
    out[w * OUTC + lane] = x0 - mx - lse;
    if (hi) out[w * OUTC + lane + 32] = x1 - mx - lse;
}

// ---------------- launch ---------------------------------------------------
extern "C" void kernel_launch(void* const* d_in, const int* in_sizes, int n_in,
                              void* d_out, int out_size) {
    const float* x     = (const float*)d_in[0];
    const int*   n_id1 = (const int*)d_in[1];
    const int*   res1  = (const int*)d_in[2];
    const int*   esrc1 = (const int*)d_in[3];
    const int*   edst1 = (const int*)d_in[4];
    const int*   res2  = (const int*)d_in[5];
    const int*   esrc2 = (const int*)d_in[6];
    const int*   edst2 = (const int*)d_in[7];
    const float* W1    = (const float*)d_in[8];
    const float* asw1  = (const float*)d_in[9];
    const float* adw1  = (const float*)d_in[10];
    const float* b1    = (const float*)d_in[11];
    const float* W2    = (const float*)d_in[12];
    const float* asw2  = (const float*)d_in[13];
    const float* adw2  = (const float*)d_in[14];
    const float* b2    = (const float*)d_in[15];
    float* out = (float*)d_out;

    // Layer 1
    k_gemm1<<<(N1 + 255) / 256, 256>>>(x, n_id1, W1, asw1);
    k_ad1<<<(N1D * H1 + 255) / 256, 256>>>(res1, adw1);
    k_zero<<<(N1D + 255) / 256, 256>>>();
    k_hist<<<(E1 + 255) / 256, 256>>>(edst1, E1);
    k_scan<<<1, 1024>>>(N1D, 0);
    k_scatter<<<(E1 + 255) / 256, 256>>>(edst1, esrc1, E1, 0);
    k_agg1<<<(N1D + 7) / 8, 256>>>(b1);
    // Layer 2
    k_gemm2<<<(N1D + 31) / 32, 256>>>(W2);
    k_asad2<<<(N1D + N2D + 255) / 256, 256>>>(res2, asw2, adw2);
    k_zero<<<(N1D + 255) / 256, 256>>>();
    k_hist<<<(E2 + 255) / 256, 256>>>(edst2, E2);
    k_scan<<<1, 1024>>>(N2D, 1);
    k_scatter<<<(E2 + 255) / 256, 256>>>(edst2, esrc2, E2, 1);
    k_agg2<<<(N2D + 7) / 8, 256>>>(b2, out);
}

// round 2
// speedup vs baseline: 1.4444x; 1.4444x over previous
#include <cuda_runtime.h>
#include <cuda_bf16.h>
#include <math.h>
#include <float.h>
#include <stdint.h>

// Problem-fixed shapes (from reference setup_inputs)
#define N_TOT   200000
#define F_IN    602
#define N1      120000
#define N1D     30000
#define E1      960000
#define N2D     6000
#define E2      192000
#define C1      64
#define H1      8
#define OUTC    41

// ---------------- scratch (static device globals; no allocation) ------------
__device__ float g_hs1[(size_t)N1 * C1];     // layer-1 transformed features
__device__ float g_as1[N1 * H1];             // per-node src attention logits
__device__ float g_ad1[N1D * H1];            // per-dst-node dst attention logits
__device__ float g_out1[N1D * C1];           // layer-1 output (post bias+ELU)
__device__ float g_hs2[N1D * OUTC];          // layer-2 transformed features
__device__ float g_as2[N1D];
__device__ float g_ad2[N2D];
__device__ int   g_counts[N1D];
__device__ int   g_cursor[N1D];
__device__ int   g_offs1[N1D + 1];
__device__ int   g_offs2[N2D + 1];
__device__ int   g_ssrc1[E1];                // edge src sorted by dst
__device__ int   g_ssrc2[E2];

// ---------------- tensor-core helpers --------------------------------------
__device__ __forceinline__ uint32_t smem_u32(const void* p) {
    return (uint32_t)__cvta_generic_to_shared(p);
}
__device__ __forceinline__ void ldsm_x4(uint32_t& r0, uint32_t& r1, uint32_t& r2,
                                        uint32_t& r3, uint32_t addr) {
    asm volatile("ldmatrix.sync.aligned.m8n8.x4.shared.b16 {%0,%1,%2,%3},[%4];"
                 : "=r"(r0), "=r"(r1), "=r"(r2), "=r"(r3) : "r"(addr));
}
__device__ __forceinline__ void ldsm_x2t(uint32_t& r0, uint32_t& r1, uint32_t addr) {
    asm volatile("ldmatrix.sync.aligned.m8n8.x2.trans.shared.b16 {%0,%1},[%2];"
                 : "=r"(r0), "=r"(r1) : "r"(addr));
}
__device__ __forceinline__ void mma_bf16(float* c, const uint32_t* a, const uint32_t* b) {
    asm volatile("mma.sync.aligned.m16n8k16.row.col.f32.bf16.bf16.f32 "
                 "{%0,%1,%2,%3},{%4,%5,%6,%7},{%8,%9},{%0,%1,%2,%3};"
                 : "+f"(c[0]), "+f"(c[1]), "+f"(c[2]), "+f"(c[3])
                 : "r"(a[0]), "r"(a[1]), "r"(a[2]), "r"(a[3]), "r"(b[0]), "r"(b[1]));
}

// ---------------- GEMM1 (tensor-core, split-bf16): hs1 = x[n_id1] @ W1 ------
// Block 256 thr (8 warps), tile 128 rows x 64 cols, K-chunks of 16 (38 chunks).
// Split: v = hi(bf16) + lo(bf16); D = Ah*Bh + Ah*Bl + Al*Bh (fp32 accum).
// Fused epilogue computes as1 = sum_c hs1*att_src per (row, head).
#define APITCH 24
#define BPITCH 72
#define NCHUNK 38

__global__ __launch_bounds__(256, 2)
void k_gemm1_mma(const float* __restrict__ x, const int* __restrict__ n_id,
                 const float* __restrict__ W, const float* __restrict__ att_src) {
    __shared__ __align__(16) __nv_bfloat16 Ah[128 * APITCH];
    __shared__ __align__(16) __nv_bfloat16 Al[128 * APITCH];
    __shared__ __align__(16) __nv_bfloat16 Bh[16 * BPITCH];
    __shared__ __align__(16) __nv_bfloat16 Bl[16 * BPITCH];
    __shared__ int   rid[128];
    __shared__ float att[64];

    int tid = threadIdx.x;
    int row0 = blockIdx.x * 128;
    if (tid < 128) { int r = row0 + tid; rid[tid] = (r < N1) ? n_id[r] : -1; }
    if (tid < 64) att[tid] = att_src[tid];
    __syncthreads();

    // A load role: thread t handles row t/2, cols (t&1)*8 .. +8 (8 floats)
    int arow = tid >> 1, acol = (tid & 1) * 8;
    int myr = rid[arow];
    const float* xrow = x + (myr < 0 ? 0 : (size_t)myr * F_IN);
    // B load role: thread t handles W[k0 + t/16][(t&15)*4 .. +4]
    int brow = tid >> 4, bcol = (tid & 15) * 4;

    float a_reg[8], b_reg[4];
    auto loadA = [&](int k0) {
        if (myr < 0) {
#pragma unroll
            for (int i = 0; i < 8; i++) a_reg[i] = 0.f;
        } else if (k0 + 16 <= 592) {  // fully in-bounds chunk
            const float2* p = (const float2*)(xrow + k0 + acol);
            float2 v0 = p[0], v1 = p[1], v2 = p[2], v3 = p[3];
            a_reg[0] = v0.x; a_reg[1] = v0.y; a_reg[2] = v1.x; a_reg[3] = v1.y;
            a_reg[4] = v2.x; a_reg[5] = v2.y; a_reg[6] = v3.x; a_reg[7] = v3.y;
        } else {
#pragma unroll
            for (int i = 0; i < 8; i++) {
                int kk = k0 + acol + i;
                a_reg[i] = (kk < F_IN) ? xrow[kk] : 0.f;
            }
        }
    };
    auto loadB = [&](int k0) {
        int kk = k0 + brow;
        if (kk < F_IN) {
            float4 v = *(const float4*)(W + (size_t)kk * 64 + bcol);
            b_reg[0] = v.x; b_reg[1] = v.y; b_reg[2] = v.z; b_reg[3] = v.w;
        } else {
            b_reg[0] = b_reg[1] = b_reg[2] = b_reg[3] = 0.f;
        }
    };

    float acc[8][4];
#pragma unroll
    for (int n = 0; n < 8; n++)
#pragma unroll
        for (int i = 0; i < 4; i++) acc[n][i] = 0.f;

    int warp = tid >> 5, lane = tid & 31;
    uint32_t aOffH = smem_u32(&Ah[(warp * 16 + (lane & 15)) * APITCH + (lane >> 4) * 8]);
    uint32_t aOffL = smem_u32(&Al[(warp * 16 + (lane & 15)) * APITCH + (lane >> 4) * 8]);
    int bRowOff = (lane & 15) * BPITCH;

    loadA(0); loadB(0);

    for (int c = 0; c < NCHUNK; c++) {
        // commit prefetched chunk to smem (with bf16 split)
#pragma unroll
        for (int i = 0; i < 8; i++) {
            float v = a_reg[i];
            __nv_bfloat16 h = __float2bfloat16_rn(v);
            Ah[arow * APITCH + acol + i] = h;
            Al[arow * APITCH + acol + i] = __float2bfloat16_rn(v - __bfloat162float(h));
        }
#pragma unroll
        for (int i = 0; i < 4; i++) {
            float v = b_reg[i];
            __nv_bfloat16 h = __float2bfloat16_rn(v);
            Bh[brow * BPITCH + bcol + i] = h;
            Bl[brow * BPITCH + bcol + i] = __float2bfloat16_rn(v - __bfloat162float(h));
        }
        __syncthreads();
        if (c + 1 < NCHUNK) { loadA((c + 1) * 16); loadB((c + 1) * 16); }

        uint32_t ah[4], al[4];
        ldsm_x4(ah[0], ah[1], ah[2], ah[3], aOffH);
        ldsm_x4(al[0], al[1], al[2], al[3], aOffL);
#pragma unroll
        for (int nt = 0; nt < 8; nt++) {
            uint32_t bh[2], bl[2];
            ldsm_x2t(bh[0], bh[1], smem_u32(&Bh[bRowOff + nt * 8]));
            ldsm_x2t(bl[0], bl[1], smem_u32(&Bl[bRowOff + nt * 8]));
            mma_bf16(acc[nt], ah, bh);
            mma_bf16(acc[nt], ah, bl);
            mma_bf16(acc[nt], al, bh);
        }
        __syncthreads();
    }

    // Epilogue: store hs1 + fused per-head att_src dot (as1)
    int q = lane >> 2;            // row-in-8
    int c2 = (lane & 3) * 2;      // col pair within n8 tile
    int rA = row0 + warp * 16 + q;
    int rB = rA + 8;
#pragma unroll
    for (int nt = 0; nt < 8; nt++) {
        float av0 = att[nt * 8 + c2], av1 = att[nt * 8 + c2 + 1];
        float pA = acc[nt][0] * av0 + acc[nt][1] * av1;
        float pB = acc[nt][2] * av0 + acc[nt][3] * av1;
        pA += __shfl_xor_sync(0xffffffffu, pA, 1);
        pA += __shfl_xor_sync(0xffffffffu, pA, 2);
        pB += __shfl_xor_sync(0xffffffffu, pB, 1);
        pB += __shfl_xor_sync(0xffffffffu, pB, 2);
        if (rA < N1) {
            *(float2*)&g_hs1[(size_t)rA * 64 + nt * 8 + c2] = make_float2(acc[nt][0], acc[nt][1]);
            if ((lane & 3) == 0) g_as1[rA * 8 + nt] = pA;
        }
        if (rB < N1) {
            *(float2*)&g_hs1[(size_t)rB * 64 + nt * 8 + c2] = make_float2(acc[nt][2], acc[nt][3]);
            if ((lane & 3) == 0) g_as1[rB * 8 + nt] = pB;
        }
    }
}

// ---------------- ad1: per-dst attention logits ----------------------------
__global__ void k_ad1(const int* __restrict__ res1, const float* __restrict__ att_dst) {
    int idx = blockIdx.x * blockDim.x + threadIdx.x;
    if (idx >= N1D * H1) return;
    int j = idx >> 3, h = idx & 7;
    int node = res1[j];
    const float* hp = &g_hs1[(size_t)node * 64 + h * 8];
    const float* ap = &att_dst[h * 8];
    float s = 0.f;
#pragma unroll
    for (int c = 0; c < 8; c++) s = fmaf(hp[c], ap[c], s);
    g_ad1[idx] = s;
}

// ---------------- CSR build ------------------------------------------------
__global__ void k_zero() {
    int i = blockIdx.x * blockDim.x + threadIdx.x;
    if (i < N1D) { g_counts[i] = 0; g_cursor[i] = 0; }
}

__global__ void k_hist(const int* __restrict__ dst, int E) {
    int i = blockIdx.x * blockDim.x + threadIdx.x;
    if (i < E) atomicAdd(&g_counts[dst[i]], 1);
}

__global__ void k_scan(int n, int layer) {
    __shared__ int sh[1024];
    int tid = threadIdx.x;
    int* offs = layer ? g_offs2 : g_offs1;
    int ipt = (n + 1023) / 1024;
    int beg = tid * ipt, end = min(n, beg + ipt);
    int s = 0;
    for (int i = beg; i < end; i++) s += g_counts[i];
    sh[tid] = s;
    __syncthreads();
    for (int d = 1; d < 1024; d <<= 1) {
        int v = (tid >= d) ? sh[tid - d] : 0;
        __syncthreads();
        if (tid >= d) sh[tid] += v;
        __syncthreads();
    }
    int run = sh[tid] - s;   // exclusive prefix
    for (int i = beg; i < end; i++) { offs[i] = run; run += g_counts[i]; }
    if (tid == 1023) offs[n] = run;
}

__global__ void k_scatter(const int* __restrict__ dst, const int* __restrict__ src,
                          int E, int layer) {
    int i = blockIdx.x * blockDim.x + threadIdx.x;
    if (i >= E) return;
    int d = dst[i];
    const int* offs = layer ? g_offs2 : g_offs1;
    int* out = layer ? g_ssrc2 : g_ssrc1;
    int pos = atomicAdd(&g_cursor[d], 1);
    out[offs[d] + pos] = src[i];
}

// ---------------- layer-1 aggregation: 1 warp / dst ------------------------
__global__ void k_agg1(const float* __restrict__ bias) {
    int w = (blockIdx.x * blockDim.x + threadIdx.x) >> 5;
    int lane = threadIdx.x & 31;
    if (w >= N1D) return;
    int off0 = g_offs1[w], off1 = g_offs1[w + 1];
    int deg = off1 - off0;
    int h = lane & 7, eg = lane >> 3;
    float adh = g_ad1[w * 8 + h];
    float m = -FLT_MAX, s = 0.f;
    for (int i = eg; i < deg; i += 4) {
        int src = g_ssrc1[off0 + i];
        float e = g_as1[src * 8 + h] + adh;
        e = (e > 0.f) ? e : 0.2f * e;
        float mn = fmaxf(m, e);
        s = s * __expf(m - mn) + __expf(e - mn);
        m = mn;
    }
#pragma unroll
    for (int d2 = 8; d2 <= 16; d2 <<= 1) {
        float m2 = __shfl_xor_sync(0xffffffffu, m, d2);
        float s2 = __shfl_xor_sync(0xffffffffu, s, d2);
        float mn = fmaxf(m, m2);
        s = s * __expf(m - mn) + s2 * __expf(m2 - mn);
        m = mn;
    }
    int hc = lane >> 2;   // head for my 2 channels (cols 2*lane, 2*lane+1)
    float mh  = __shfl_sync(0xffffffffu, m, hc);
    float sh_ = __shfl_sync(0xffffffffu, s, hc);
    float inv = (sh_ > 0.f) ? 1.f / sh_ : 0.f;
    float adc = g_ad1[w * 8 + hc];
    float acc0 = 0.f, acc1 = 0.f;
    for (int i = 0; i < deg; i++) {
        int src = g_ssrc1[off0 + i];
        float e = g_as1[src * 8 + hc] + adc;
        e = (e > 0.f) ? e : 0.2f * e;
        float al = __expf(e - mh) * inv;
        float2 hv = *(const float2*)&g_hs1[(size_t)src * 64 + 2 * lane];
        acc0 = fmaf(al, hv.x, acc0);
        acc1 = fmaf(al, hv.y, acc1);
    }
    int c0 = 2 * lane;
    float v0 = acc0 + bias[c0], v1 = acc1 + bias[c0 + 1];
    v0 = (v0 > 0.f) ? v0 : expm1f(v0);   // ELU
    v1 = (v1 > 0.f) ? v1 : expm1f(v1);
    *(float2*)&g_out1[w * 64 + c0] = make_float2(v0, v1);
}

// ---------------- GEMM2: hs2 = out1 @ W2 -----------------------------------
__global__ void k_gemm2(const float* __restrict__ W2) {
    __shared__ float Asm[32][65];
    __shared__ float Wt[OUTC][65];
    int tid = threadIdx.x;
    int row0 = blockIdx.x * 32;
    for (int i = tid; i < 32 * 64; i += 256) {
        int r = i >> 6, k = i & 63;
        int row = row0 + r;
        Asm[r][k] = (row < N1D) ? g_out1[row * 64 + k] : 0.f;
    }
    for (int i = tid; i < OUTC * 64; i += 256) {
        int c = i >> 6, k = i & 63;
        Wt[c][k] = W2[k * OUTC + c];
    }
    __syncthreads();
    for (int o = tid; o < 32 * OUTC; o += 256) {
        int r = o / OUTC, c = o - r * OUTC;
        int row = row0 + r;
        if (row >= N1D) continue;
        float s = 0.f;
#pragma unroll
        for (int k = 0; k < 64; k++) s = fmaf(Asm[r][k], Wt[c][k], s);
        g_hs2[row * OUTC + c] = s;
    }
}

// ---------------- as2 / ad2 ------------------------------------------------
__global__ void k_asad2(const int* __restrict__ res2, const float* __restrict__ asw,
                        const float* __restrict__ adw) {
    int i = blockIdx.x * blockDim.x + threadIdx.x;
    if (i < N1D) {
        const float* hp = &g_hs2[i * OUTC];
        float s = 0.f;
#pragma unroll
        for (int c = 0; c < OUTC; c++) s = fmaf(hp[c], asw[c], s);
        g_as2[i] = s;
    } else if (i < N1D + N2D) {
        int j = i - N1D;
        const float* hp = &g_hs2[res2[j] * OUTC];
        float s = 0.f;
#pragma unroll
        for (int c = 0; c < OUTC; c++) s = fmaf(hp[c], adw[c], s);
        g_ad2[j] = s;
    }
}

// ---------------- layer-2 aggregation + log_softmax: 1 warp / dst ----------
__global__ void k_agg2(const float* __restrict__ bias, float* __restrict__ out) {
    int w = (blockIdx.x * blockDim.x + threadIdx.x) >> 5;
    int lane = threadIdx.x & 31;
    if (w >= N2D) return;
    int off0 = g_offs2[w], off1 = g_offs2[w + 1];
    int deg = off1 - off0;
    float add = g_ad2[w];
    float m = -FLT_MAX, s = 0.f;
    for (int i = lane; i < deg; i += 32) {
        int src = g_ssrc2[off0 + i];
        float e = g_as2[src] + add;
        e = (e > 0.f) ? e : 0.2f * e;
        float mn = fmaxf(m, e);
        s = s * __expf(m - mn) + __expf(e - mn);
        m = mn;
    }
#pragma unroll
    for (int d2 = 1; d2 < 32; d2 <<= 1) {
        float m2 = __shfl_xor_sync(0xffffffffu, m, d2);
        float s2 = __shfl_xor_sync(0xffffffffu, s, d2);
        float mn = fmaxf(m, m2);
        s = s * __expf(m - mn) + s2 * __expf(m2 - mn);
        m = mn;
    }
    float inv = (s > 0.f) ? 1.f / s : 0.f;
    float acc0 = 0.f, acc1 = 0.f;
    bool hi = (lane + 32) < OUTC;
    for (int i = 0; i < deg; i++) {
        int src = g_ssrc2[off0 + i];
        float e = g_as2[src] + add;
        e = (e > 0.f) ? e : 0.2f * e;
        float al = __expf(e - m) * inv;
        const float* hp = &g_hs2[src * OUTC];
        acc0 = fmaf(al, hp[lane], acc0);
        if (hi) acc1 = fmaf(al, hp[lane + 32], acc1);
    }
    float x0 = acc0 + bias[lane];
    float x1 = hi ? (acc1 + bias[lane + 32]) : -FLT_MAX;
    // log_softmax over 41 columns
    float mx = fmaxf(x0, x1);
#pragma unroll
    for (int d2 = 1; d2 < 32; d2 <<= 1) mx = fmaxf(mx, __shfl_xor_sync(0xffffffffu, mx, d2));
    float se = expf(x0 - mx) + (hi ? expf(x1 - mx) : 0.f);
#pragma unroll
    for (int d2 = 1; d2 < 32; d2 <<= 1) se += __shfl_xor_sync(0xffffffffu, se, d2);
    float lse = logf(se);
    out[w * OUTC + lane] = x0 - mx - lse;
    if (hi) out[w * OUTC + lane + 32] = x1 - mx - lse;
}

// ---------------- launch ---------------------------------------------------
extern "C" void kernel_launch(void* const* d_in, const int* in_sizes, int n_in,
                              void* d_out, int out_size) {
    const float* x     = (const float*)d_in[0];
    const int*   n_id1 = (const int*)d_in[1];
    const int*   res1  = (const int*)d_in[2];
    const int*   esrc1 = (const int*)d_in[3];
    const int*   edst1 = (const int*)d_in[4];
    const int*   res2  = (const int*)d_in[5];
    const int*   esrc2 = (const int*)d_in[6];
    const int*   edst2 = (const int*)d_in[7];
    const float* W1    = (const float*)d_in[8];
    const float* asw1  = (const float*)d_in[9];
    const float* adw1  = (const float*)d_in[10];
    const float* b1    = (const float*)d_in[11];
    const float* W2    = (const float*)d_in[12];
    const float* asw2  = (const float*)d_in[13];
    const float* adw2  = (const float*)d_in[14];
    const float* b2    = (const float*)d_in[15];
    float* out = (float*)d_out;

    // Layer 1
    k_gemm1_mma<<<(N1 + 127) / 128, 256>>>(x, n_id1, W1, asw1);
    k_ad1<<<(N1D * H1 + 255) / 256, 256>>>(res1, adw1);
    k_zero<<<(N1D + 255) / 256, 256>>>();
    k_hist<<<(E1 + 255) / 256, 256>>>(edst1, E1);
    k_scan<<<1, 1024>>>(N1D, 0);
    k_scatter<<<(E1 + 255) / 256, 256>>>(edst1, esrc1, E1, 0);
    k_agg1<<<(N1D + 7) / 8, 256>>>(b1);
    // Layer 2
    k_gemm2<<<(N1D + 31) / 32, 256>>>(W2);
    k_asad2<<<(N1D + N2D + 255) / 256, 256>>>(res2, asw2, adw2);
    k_zero<<<(N1D + 255) / 256, 256>>>();
    k_hist<<<(E2 + 255) / 256, 256>>>(edst2, E2);
    k_scan<<<1, 1024>>>(N2D, 1);
    k_scatter<<<(E2 + 255) / 256, 256>>>(edst2, esrc2, E2, 1);
    k_agg2<<<(N2D + 7) / 8, 256>>>(b2, out);
}

// round 3
// speedup vs baseline: 1.5839x; 1.0966x over previous
#include <cuda_runtime.h>
#include <cuda_bf16.h>
#include <math.h>
#include <float.h>
#include <stdint.h>

// Problem-fixed shapes (from reference setup_inputs)
#define N_TOT   200000
#define F_IN    602
#define N1      120000
#define N1D     30000
#define E1      960000
#define N2D     6000
#define E2      192000
#define C1      64
#define H1      8
#define OUTC    41

// ---------------- scratch (static device globals; no allocation) ------------
__device__ float g_hs1[(size_t)N1 * C1];
__device__ float g_as1[N1 * H1];
__device__ float g_ad1[N1D * H1];
__device__ float g_out1[N1D * C1];
__device__ float g_hs2[N1D * OUTC];
__device__ float g_as2[N1D];
__device__ int   g_counts[N1D];
__device__ int   g_cursor[N1D];
__device__ int   g_counts2[N2D];
__device__ int   g_cursor2[N2D];
__device__ int   g_offs1[N1D + 1];
__device__ int   g_offs2[N2D + 1];
__device__ int   g_ssrc1[E1];
__device__ int   g_ssrc2[E2];

// ---------------- tensor-core helpers --------------------------------------
__device__ __forceinline__ uint32_t smem_u32(const void* p) {
    return (uint32_t)__cvta_generic_to_shared(p);
}
__device__ __forceinline__ void ldsm_x4(uint32_t* r, uint32_t addr) {
    asm volatile("ldmatrix.sync.aligned.m8n8.x4.shared.b16 {%0,%1,%2,%3},[%4];"
                 : "=r"(r[0]), "=r"(r[1]), "=r"(r[2]), "=r"(r[3]) : "r"(addr));
}
__device__ __forceinline__ void ldsm_x4t(uint32_t* r, uint32_t addr) {
    asm volatile("ldmatrix.sync.aligned.m8n8.x4.trans.shared.b16 {%0,%1,%2,%3},[%4];"
                 : "=r"(r[0]), "=r"(r[1]), "=r"(r[2]), "=r"(r[3]) : "r"(addr));
}
__device__ __forceinline__ void mma_bf16(float* c, const uint32_t* a, const uint32_t* b) {
    asm volatile("mma.sync.aligned.m16n8k16.row.col.f32.bf16.bf16.f32 "
                 "{%0,%1,%2,%3},{%4,%5,%6,%7},{%8,%9},{%0,%1,%2,%3};"
                 : "+f"(c[0]), "+f"(c[1]), "+f"(c[2]), "+f"(c[3])
                 : "r"(a[0]), "r"(a[1]), "r"(a[2]), "r"(a[3]), "r"(b[0]), "r"(b[1]));
}

// ---------------- mega kernel: GEMM1 (split-bf16 MMA) + both histograms ----
// GEMM blocks: 256 thr, tile 128x64, K-chunk 32, double-buffered smem.
// Split: v = hi + lo (bf16); D = Ah*Bh + Ah*Bl + Al*Bh (fp32 accum).
#define GEMM_BLOCKS ((N1 + 127) / 128)     /* 938 */
#define HIST_BLOCKS 512
#define APITCH 40
#define BPITCH 72
#define KC     32
#define NCHUNK 19
// smem byte offsets (all 16B aligned)
#define A_BUF_BYTES 10240                  /* 128*40*2 */
#define B_BUF_BYTES 4608                   /* 32*72*2 */
#define AH_OFF 0
#define AL_OFF 20480
#define BH_OFF 40960
#define BL_OFF 50176
#define RID_OFF 59392
#define ATT_OFF 59904
#define SMEM_BYTES 60160

__global__ __launch_bounds__(256)
void k_mega(const float* __restrict__ x, const int* __restrict__ n_id,
            const float* __restrict__ W, const float* __restrict__ att_src,
            const int* __restrict__ edst1, const int* __restrict__ edst2) {
    extern __shared__ char sm[];
    int tid = threadIdx.x;

    if (blockIdx.x >= GEMM_BLOCKS) {
        // -------- histogram path (both layers) --------
        int i = (blockIdx.x - GEMM_BLOCKS) * 256 + tid;
        int stride = HIST_BLOCKS * 256;
        for (; i < E1 + E2; i += stride) {
            if (i < E1) atomicAdd(&g_counts[edst1[i]], 1);
            else        atomicAdd(&g_counts2[edst2[i - E1]], 1);
        }
        return;
    }

    int*   rid = (int*)(sm + RID_OFF);
    float* att = (float*)(sm + ATT_OFF);
    int row0 = blockIdx.x * 128;
    if (tid < 128) { int r = row0 + tid; rid[tid] = (r < N1) ? n_id[r] : -1; }
    if (tid < 64) att[tid] = att_src[tid];
    __syncthreads();

    // A loader: thread t handles row (t&127), cols (t>>7)*16 .. +16
    int arow = tid & 127, acolb = (tid >> 7) * 16;
    int myr = rid[arow];
    const float* xrow = x + (myr < 0 ? 0 : (size_t)myr * F_IN);
    // B loader: thread t handles W row k0+(t>>3), cols (t&7)*8 .. +8
    int brow = tid >> 3, bcolb = (tid & 7) * 8;

    float a_reg[16], b_reg[8];
    auto loadA = [&](int k0) {
        if (myr < 0) {
#pragma unroll
            for (int i = 0; i < 16; i++) a_reg[i] = 0.f;
        } else if (k0 + KC <= F_IN) {
            const float2* p = (const float2*)(xrow + k0 + acolb);
#pragma unroll
            for (int j = 0; j < 8; j++) { float2 v = p[j]; a_reg[2*j] = v.x; a_reg[2*j+1] = v.y; }
        } else {
#pragma unroll
            for (int i = 0; i < 16; i++) {
                int kk = k0 + acolb + i;
                a_reg[i] = (kk < F_IN) ? xrow[kk] : 0.f;
            }
        }
    };
    auto loadB = [&](int k0) {
        int kk = k0 + brow;
        if (kk < F_IN) {
            const float4* p = (const float4*)(W + (size_t)kk * 64 + bcolb);
            float4 v0 = p[0], v1 = p[1];
            b_reg[0]=v0.x; b_reg[1]=v0.y; b_reg[2]=v0.z; b_reg[3]=v0.w;
            b_reg[4]=v1.x; b_reg[5]=v1.y; b_reg[6]=v1.z; b_reg[7]=v1.w;
        } else {
#pragma unroll
            for (int i = 0; i < 8; i++) b_reg[i] = 0.f;
        }
    };
    auto storeA = [&](int buf) {
        char* bh = sm + AH_OFF + buf * A_BUF_BYTES;
        char* bl = sm + AL_OFF + buf * A_BUF_BYTES;
#pragma unroll
        for (int q = 0; q < 2; q++) {
            uint32_t hw[4], lw[4];
#pragma unroll
            for (int j = 0; j < 4; j++) {
                float x0 = a_reg[q*8 + 2*j], x1 = a_reg[q*8 + 2*j + 1];
                __nv_bfloat162 h2 = __floats2bfloat162_rn(x0, x1);
                float l0 = x0 - __bfloat162float(__low2bfloat16(h2));
                float l1 = x1 - __bfloat162float(__high2bfloat16(h2));
                __nv_bfloat162 l2 = __floats2bfloat162_rn(l0, l1);
                hw[j] = *(uint32_t*)&h2; lw[j] = *(uint32_t*)&l2;
            }
            int off = (arow * APITCH + acolb + q * 8) * 2;
            *(uint4*)(bh + off) = make_uint4(hw[0], hw[1], hw[2], hw[3]);
            *(uint4*)(bl + off) = make_uint4(lw[0], lw[1], lw[2], lw[3]);
        }
    };
    auto storeB = [&](int buf) {
        char* bh = sm + BH_OFF + buf * B_BUF_BYTES;
        char* bl = sm + BL_OFF + buf * B_BUF_BYTES;
        uint32_t hw[4], lw[4];
#pragma unroll
        for (int j = 0; j < 4; j++) {
            float x0 = b_reg[2*j], x1 = b_reg[2*j + 1];
            __nv_bfloat162 h2 = __floats2bfloat162_rn(x0, x1);
            float l0 = x0 - __bfloat162float(__low2bfloat16(h2));
            float l1 = x1 - __bfloat162float(__high2bfloat16(h2));
            __nv_bfloat162 l2 = __floats2bfloat162_rn(l0, l1);
            hw[j] = *(uint32_t*)&h2; lw[j] = *(uint32_t*)&l2;
        }
        int off = (brow * BPITCH + bcolb) * 2;
        *(uint4*)(bh + off) = make_uint4(hw[0], hw[1], hw[2], hw[3]);
        *(uint4*)(bl + off) = make_uint4(lw[0], lw[1], lw[2], lw[3]);
    };

    float acc[8][4];
#pragma unroll
    for (int n = 0; n < 8; n++)
#pragma unroll
        for (int i = 0; i < 4; i++) acc[n][i] = 0.f;

    int warp = tid >> 5, lane = tid & 31;
    int aRowSel = ((warp * 16 + (lane & 15)) * APITCH + (lane >> 4) * 8) * 2;  // bytes
    int bRowSel = ((lane & 15) * BPITCH + (lane >> 4) * 8) * 2;                // bytes

    loadA(0); loadB(0); storeA(0); storeB(0);

    for (int c = 0; c < NCHUNK; c++) {
        __syncthreads();
        int buf = c & 1;
        if (c + 1 < NCHUNK) { loadA((c + 1) * KC); loadB((c + 1) * KC); }

        uint32_t aH = smem_u32(sm + AH_OFF + buf * A_BUF_BYTES) + aRowSel;
        uint32_t aL = smem_u32(sm + AL_OFF + buf * A_BUF_BYTES) + aRowSel;
        uint32_t bH = smem_u32(sm + BH_OFF + buf * B_BUF_BYTES) + bRowSel;
        uint32_t bL = smem_u32(sm + BL_OFF + buf * B_BUF_BYTES) + bRowSel;
#pragma unroll
        for (int ks = 0; ks < 2; ks++) {
            uint32_t ah[4], al[4];
            ldsm_x4(ah, aH + ks * 32);
            ldsm_x4(al, aL + ks * 32);
            uint32_t bko = (uint32_t)(ks * 16 * BPITCH * 2);
#pragma unroll
            for (int p = 0; p < 4; p++) {
                uint32_t bh[4], bl[4];
                ldsm_x4t(bh, bH + bko + p * 32);
                ldsm_x4t(bl, bL + bko + p * 32);
                mma_bf16(acc[2*p],     ah, bh);
                mma_bf16(acc[2*p],     ah, bl);
                mma_bf16(acc[2*p],     al, bh);
                mma_bf16(acc[2*p + 1], ah, bh + 2);
                mma_bf16(acc[2*p + 1], ah, bl + 2);
                mma_bf16(acc[2*p + 1], al, bh + 2);
            }
        }
        if (c + 1 < NCHUNK) { storeA(buf ^ 1); storeB(buf ^ 1); }
    }

    // Epilogue: store hs1 + fused per-head att_src dot (as1)
    int q = lane >> 2;
    int c2 = (lane & 3) * 2;
    int rA = row0 + warp * 16 + q;
    int rB = rA + 8;
#pragma unroll
    for (int nt = 0; nt < 8; nt++) {
        float av0 = att[nt * 8 + c2], av1 = att[nt * 8 + c2 + 1];
        float pA = acc[nt][0] * av0 + acc[nt][1] * av1;
        float pB = acc[nt][2] * av0 + acc[nt][3] * av1;
        pA += __shfl_xor_sync(0xffffffffu, pA, 1);
        pA += __shfl_xor_sync(0xffffffffu, pA, 2);
        pB += __shfl_xor_sync(0xffffffffu, pB, 1);
        pB += __shfl_xor_sync(0xffffffffu, pB, 2);
        if (rA < N1) {
            *(float2*)&g_hs1[(size_t)rA * 64 + nt * 8 + c2] = make_float2(acc[nt][0], acc[nt][1]);
            if ((lane & 3) == 0) g_as1[rA * 8 + nt] = pA;
        }
        if (rB < N1) {
            *(float2*)&g_hs1[(size_t)rB * 64 + nt * 8 + c2] = make_float2(acc[nt][2], acc[nt][3]);
            if ((lane & 3) == 0) g_as1[rB * 8 + nt] = pB;
        }
    }
}

// ---------------- zero counters --------------------------------------------
__global__ void k_zero_all() {
    int i = blockIdx.x * blockDim.x + threadIdx.x;
    if (i < N1D) { g_counts[i] = 0; g_cursor[i] = 0; }
    if (i < N2D) { g_counts2[i] = 0; g_cursor2[i] = 0; }
}

// ---------------- scan (both layers, one kernel) ---------------------------
__global__ void k_scan_both() {
    __shared__ int sh[1024];
    int tid = threadIdx.x;
    int n     = (blockIdx.x == 0) ? N1D : N2D;
    int* cnt  = (blockIdx.x == 0) ? g_counts : g_counts2;
    int* offs = (blockIdx.x == 0) ? g_offs1 : g_offs2;
    int ipt = (n + 1023) / 1024;
    int beg = tid * ipt, end = min(n, beg + ipt);
    int s = 0;
    for (int i = beg; i < end; i++) s += cnt[i];
    sh[tid] = s;
    __syncthreads();
    for (int d = 1; d < 1024; d <<= 1) {
        int v = (tid >= d) ? sh[tid - d] : 0;
        __syncthreads();
        if (tid >= d) sh[tid] += v;
        __syncthreads();
    }
    int run = sh[tid] - s;
    for (int i = beg; i < end; i++) { offs[i] = run; run += cnt[i]; }
    if (tid == 1023) offs[n] = run;
}

// ---------------- scatter (both layers) + ad1 fused -------------------------
__global__ void k_scatter_ad1(const int* __restrict__ esrc1, const int* __restrict__ edst1,
                              const int* __restrict__ esrc2, const int* __restrict__ edst2,
                              const int* __restrict__ res1, const float* __restrict__ att_dst) {
    int i = blockIdx.x * blockDim.x + threadIdx.x;
    if (i < E1) {
        int d = edst1[i];
        int pos = atomicAdd(&g_cursor[d], 1);
        g_ssrc1[g_offs1[d] + pos] = esrc1[i];
    } else if (i < E1 + E2) {
        int j = i - E1;
        int d = edst2[j];
        int pos = atomicAdd(&g_cursor2[d], 1);
        g_ssrc2[g_offs2[d] + pos] = esrc2[j];
    } else if (i < E1 + E2 + N1D * H1) {
        int idx = i - (E1 + E2);
        int j = idx >> 3, h = idx & 7;
        int node = res1[j];
        const float* hp = &g_hs1[(size_t)node * 64 + h * 8];
        const float* ap = &att_dst[h * 8];
        float s = 0.f;
#pragma unroll
        for (int c = 0; c < 8; c++) s = fmaf(hp[c], ap[c], s);
        g_ad1[idx] = s;
    }
}

// ---------------- layer-1 aggregation: 1 warp / dst ------------------------
__global__ void k_agg1(const float* __restrict__ bias) {
    int w = (blockIdx.x * blockDim.x + threadIdx.x) >> 5;
    int lane = threadIdx.x & 31;
    if (w >= N1D) return;
    int off0 = g_offs1[w], off1 = g_offs1[w + 1];
    int deg = off1 - off0;
    int h = lane & 7, eg = lane >> 3;
    float adh = g_ad1[w * 8 + h];
    float m = -FLT_MAX, s = 0.f;
    for (int i = eg; i < deg; i += 4) {
        int src = g_ssrc1[off0 + i];
        float e = g_as1[src * 8 + h] + adh;
        e = (e > 0.f) ? e : 0.2f * e;
        float mn = fmaxf(m, e);
        s = s * __expf(m - mn) + __expf(e - mn);
        m = mn;
    }
#pragma unroll
    for (int d2 = 8; d2 <= 16; d2 <<= 1) {
        float m2 = __shfl_xor_sync(0xffffffffu, m, d2);
        float s2 = __shfl_xor_sync(0xffffffffu, s, d2);
        float mn = fmaxf(m, m2);
        s = s * __expf(m - mn) + s2 * __expf(m2 - mn);
        m = mn;
    }
    int hc = lane >> 2;
    float mh  = __shfl_sync(0xffffffffu, m, hc);
    float sh_ = __shfl_sync(0xffffffffu, s, hc);
    float inv = (sh_ > 0.f) ? 1.f / sh_ : 0.f;
    float adc = g_ad1[w * 8 + hc];
    float acc0 = 0.f, acc1 = 0.f;
    for (int i = 0; i < deg; i++) {
        int src = g_ssrc1[off0 + i];
        float e = g_as1[src * 8 + hc] + adc;
        e = (e > 0.f) ? e : 0.2f * e;
        float al = __expf(e - mh) * inv;
        float2 hv = *(const float2*)&g_hs1[(size_t)src * 64 + 2 * lane];
        acc0 = fmaf(al, hv.x, acc0);
        acc1 = fmaf(al, hv.y, acc1);
    }
    int c0 = 2 * lane;
    float v0 = acc0 + bias[c0], v1 = acc1 + bias[c0 + 1];
    v0 = (v0 > 0.f) ? v0 : expm1f(v0);
    v1 = (v1 > 0.f) ? v1 : expm1f(v1);
    *(float2*)&g_out1[w * 64 + c0] = make_float2(v0, v1);
}

// ---------------- GEMM2 (+ fused as2): hs2 = out1 @ W2 ----------------------
__global__ void k_gemm2(const float* __restrict__ W2, const float* __restrict__ asw2) {
    __shared__ float Asm[32][65];
    __shared__ float Wt[OUTC][65];
    __shared__ float Hs[32][44];
    __shared__ float av[OUTC];
    int tid = threadIdx.x;
    int row0 = blockIdx.x * 32;
    for (int i = tid; i < 32 * 64; i += 256) {
        int r = i >> 6, k = i & 63;
        int row = row0 + r;
        Asm[r][k] = (row < N1D) ? g_out1[row * 64 + k] : 0.f;
    }
    for (int i = tid; i < OUTC * 64; i += 256) {
        int c = i >> 6, k = i & 63;
        Wt[c][k] = W2[k * OUTC + c];
    }
    if (tid < OUTC) av[tid] = asw2[tid];
    __syncthreads();
    for (int o = tid; o < 32 * OUTC; o += 256) {
        int r = o / OUTC, c = o - r * OUTC;
        int row = row0 + r;
        float s = 0.f;
#pragma unroll
        for (int k = 0; k < 64; k++) s = fmaf(Asm[r][k], Wt[c][k], s);
        Hs[r][c] = s;
        if (row < N1D) g_hs2[row * OUTC + c] = s;
    }
    __syncthreads();
    if (tid < 32 && row0 + tid < N1D) {
        float s = 0.f;
#pragma unroll
        for (int c = 0; c < OUTC; c++) s = fmaf(Hs[tid][c], av[c], s);
        g_as2[row0 + tid] = s;
    }
}

// ---------------- layer-2 aggregation (+ad2 prologue) + log_softmax --------
__global__ void k_agg2(const float* __restrict__ bias, const float* __restrict__ adw2,
                       const int* __restrict__ res2, float* __restrict__ out) {
    int w = (blockIdx.x * blockDim.x + threadIdx.x) >> 5;
    int lane = threadIdx.x & 31;
    if (w >= N2D) return;
    // ad2 = dot(hs2[res2[w]], att_dst2), warp-cooperative
    int node = res2[w];
    float p = g_hs2[node * OUTC + lane] * adw2[lane];
    if (lane < OUTC - 32) p += g_hs2[node * OUTC + lane + 32] * adw2[lane + 32];
#pragma unroll
    for (int d2 = 16; d2; d2 >>= 1) p += __shfl_xor_sync(0xffffffffu, p, d2);
    float add = p;

    int off0 = g_offs2[w], off1 = g_offs2[w + 1];
    int deg = off1 - off0;
    float m = -FLT_MAX, s = 0.f;
    for (int i = lane; i < deg; i += 32) {
        int src = g_ssrc2[off0 + i];
        float e = g_as2[src] + add;
        e = (e > 0.f) ? e : 0.2f * e;
        float mn = fmaxf(m, e);
        s = s * __expf(m - mn) + __expf(e - mn);
        m = mn;
    }
#pragma unroll
    for (int d2 = 1; d2 < 32; d2 <<= 1) {
        float m2 = __shfl_xor_sync(0xffffffffu, m, d2);
        float s2 = __shfl_xor_sync(0xffffffffu, s, d2);
        float mn = fmaxf(m, m2);
        s = s * __expf(m - mn) + s2 * __expf(m2 - mn);
        m = mn;
    }
    float inv = (s > 0.f) ? 1.f / s : 0.f;
    float acc0 = 0.f, acc1 = 0.f;
    bool hi = (lane + 32) < OUTC;
    for (int i = 0; i < deg; i++) {
        int src = g_ssrc2[off0 + i];
        float e = g_as2[src] + add;
        e = (e > 0.f) ? e : 0.2f * e;
        float al = __expf(e - m) * inv;
        const float* hp = &g_hs2[src * OUTC];
        acc0 = fmaf(al, hp[lane], acc0);
        if (hi) acc1 = fmaf(al, hp[lane + 32], acc1);
    }
    float x0 = acc0 + bias[lane];
    float x1 = hi ? (acc1 + bias[lane + 32]) : -FLT_MAX;
    float mx = fmaxf(x0, x1);
#pragma unroll
    for (int d2 = 1; d2 < 32; d2 <<= 1) mx = fmaxf(mx, __shfl_xor_sync(0xffffffffu, mx, d2));
    float se = expf(x0 - mx) + (hi ? expf(x1 - mx) : 0.f);
#pragma unroll
    for (int d2 = 1; d2 < 32; d2 <<= 1) se += __shfl_xor_sync(0xffffffffu, se, d2);
    float lse = logf(se);
    out[w * OUTC + lane] = x0 - mx - lse;
    if (hi) out[w * OUTC + lane + 32] = x1 - mx - lse;
}

// ---------------- launch ---------------------------------------------------
extern "C" void kernel_launch(void* const* d_in, const int* in_sizes, int n_in,
                              void* d_out, int out_size) {
    const float* x     = (const float*)d_in[0];
    const int*   n_id1 = (const int*)d_in[1];
    const int*   res1  = (const int*)d_in[2];
    const int*   esrc1 = (const int*)d_in[3];
    const int*   edst1 = (const int*)d_in[4];
    const int*   res2  = (const int*)d_in[5];
    const int*   esrc2 = (const int*)d_in[6];
    const int*   edst2 = (const int*)d_in[7];
    const float* W1    = (const float*)d_in[8];
    const float* asw1  = (const float*)d_in[9];
    const float* adw1  = (const float*)d_in[10];
    const float* b1    = (const float*)d_in[11];
    const float* W2    = (const float*)d_in[12];
    const float* asw2  = (const float*)d_in[13];
    const float* adw2  = (const float*)d_in[14];
    const float* b2    = (const float*)d_in[15];
    float* out = (float*)d_out;

    cudaFuncSetAttribute(k_mega, cudaFuncAttributeMaxDynamicSharedMemorySize, SMEM_BYTES);

    k_zero_all<<<(N1D + 255) / 256, 256>>>();
    k_mega<<<GEMM_BLOCKS + HIST_BLOCKS, 256, SMEM_BYTES>>>(x, n_id1, W1, asw1, edst1, edst2);
    k_scan_both<<<2, 1024>>>();
    k_scatter_ad1<<<(E1 + E2 + N1D * H1 + 255) / 256, 256>>>(esrc1, edst1, esrc2, edst2, res1, adw1);
    k_agg1<<<(N1D + 7) / 8, 256>>>(b1);
    k_gemm2<<<(N1D + 31) / 32, 256>>>(W2, asw2);
    k_agg2<<<(N2D + 7) / 8, 256>>>(b2, adw2, res2, out);
}